// round 4
// baseline (speedup 1.0000x reference)
#include <cuda_runtime.h>
#include <cuda_bf16.h>
#include <mma.h>
#include <cstdint>

using namespace nvcuda;
using bf16 = __nv_bfloat16;

// ---------------- problem dims --------------------------------------------------
constexpr int B_  = 2;
constexpr int N_  = 2048;
constexpr int D_  = 1024;
constexpr int H_  = 8;
constexpr int DK_ = 128;
constexpr int DV_ = 1024;
constexpr int HDK = H_ * DK_;    // 1024
constexpr int HDV = H_ * DV_;    // 8192
constexpr int HN  = H_ * N_;     // 16384

// ---------------- tiling / smem config -------------------------------------------
constexpr int AST = 72;                    // K-major stage row stride (elems), BK=64
constexpr int BRST = 136;                  // row-form B stage row stride (elems)
constexpr int EP_STRIDE = 136;             // fp32 epilogue stage stride

// proj (128x256, BK=64): A 128x72 + B 256x72 per stage
constexpr int PJ_A_BYTES = 128 * AST * 2;          // 18432
constexpr int PJ_B_BYTES = 256 * AST * 2;          // 36864
constexpr int PJ_STAGE   = PJ_A_BYTES + PJ_B_BYTES;
constexpr int PJ_DSMEM   = 3 * PJ_STAGE;           // 165888

// scores (128x128, BK=64): A 128x72 + B 128x72
constexpr int SC_STAGE = 2 * 128 * AST * 2;        // 36864
constexpr int SC_DSMEM = 2 * SC_STAGE;             // 73728 (>= 69632 ep stage)

// AV (128x128, BK=64): A 128x72 + B(row) 64x136
constexpr int AV_A_BYTES = 128 * AST * 2;          // 18432
constexpr int AV_B_BYTES = 64 * BRST * 2;          // 17408
constexpr int AV_STAGE   = AV_A_BYTES + AV_B_BYTES;
constexpr int AV_DSMEM   = 3 * AV_STAGE;           // 107520

// ---------------- scratch (__device__ globals) ----------------------------------
__device__ bf16 g_xb [(size_t)B_ * N_ * D_];
__device__ bf16 g_wqb[(size_t)H_ * DK_ * D_];
__device__ bf16 g_wkb[(size_t)H_ * DK_ * D_];
__device__ bf16 g_wvb[(size_t)H_ * DV_ * D_];
__device__ bf16 g_Q  [(size_t)B_ * N_ * HDK];
__device__ bf16 g_K  [(size_t)B_ * N_ * HDK];
__device__ bf16 g_V  [(size_t)B_ * N_ * HDV];
__device__ bf16 g_sim[(size_t)B_ * N_ * HN];   // lower-triangle tiles only

// ---------------- fragment types -------------------------------------------------
using FragA  = wmma::fragment<wmma::matrix_a, 16, 16, 16, bf16, wmma::row_major>;
using FragBc = wmma::fragment<wmma::matrix_b, 16, 16, 16, bf16, wmma::col_major>;
using FragBr = wmma::fragment<wmma::matrix_b, 16, 16, 16, bf16, wmma::row_major>;
using FragC  = wmma::fragment<wmma::accumulator, 16, 16, 16, float>;

// ---------------- cp.async helpers -----------------------------------------------
__device__ __forceinline__ uint32_t smem_u32(const void* p) {
    uint32_t a;
    asm("{ .reg .u64 t; cvta.to.shared.u64 t, %1; cvt.u32.u64 %0, t; }"
        : "=r"(a) : "l"(p));
    return a;
}
__device__ __forceinline__ void cp16(uint32_t dst, const void* src) {
    asm volatile("cp.async.cg.shared.global [%0], [%1], 16;"
                 :: "r"(dst), "l"(__cvta_generic_to_global(src)));
}
__device__ __forceinline__ void cp_commit() {
    asm volatile("cp.async.commit_group;" ::: "memory");
}
__device__ __forceinline__ void cp_wait1() {
    asm volatile("cp.async.wait_group 1;" ::: "memory");
}
__device__ __forceinline__ void cp_wait0() {
    asm volatile("cp.async.wait_group 0;" ::: "memory");
}

// 128 rows x 64 cols, K-major (stride AST)
__device__ __forceinline__ void ld_A64(uint32_t sdst, const bf16* g, int ld, int tid) {
#pragma unroll
    for (int i = 0; i < 4; ++i) {
        int u = tid + i * 256;
        int r = u >> 3, c8 = u & 7;
        cp16(sdst + (uint32_t)(r * (AST * 2) + c8 * 16), g + (size_t)r * ld + c8 * 8);
    }
}
// 256 rows x 64 cols, K-major (stride AST)
__device__ __forceinline__ void ld_B64w(uint32_t sdst, const bf16* g, int ld, int tid) {
#pragma unroll
    for (int i = 0; i < 8; ++i) {
        int u = tid + i * 256;
        int r = u >> 3, c8 = u & 7;
        cp16(sdst + (uint32_t)(r * (AST * 2) + c8 * 16), g + (size_t)r * ld + c8 * 8);
    }
}
// 64 rows(k) x 128 cols(n), row-major (stride BRST)
__device__ __forceinline__ void ld_Brow64(uint32_t sdst, const bf16* g, int ld, int tid) {
#pragma unroll
    for (int i = 0; i < 4; ++i) {
        int u = tid + i * 256;
        int r = u >> 4, c16 = u & 15;
        cp16(sdst + (uint32_t)(r * (BRST * 2) + c16 * 16), g + (size_t)r * ld + c16 * 8);
    }
}

// ---------------- MMA micro-steps (BK = 64) ---------------------------------------
// warp tile 64x64, NT (B col-major view, stride AST)
__device__ __forceinline__ void mma_wide(FragC acc[4][4], const bf16* As, const bf16* Bs,
                                         int wm, int wn) {
#pragma unroll
    for (int ks = 0; ks < 64; ks += 16) {
        FragA a[4];
#pragma unroll
        for (int i = 0; i < 4; ++i)
            wmma::load_matrix_sync(a[i], As + (wm * 64 + i * 16) * AST + ks, AST);
#pragma unroll
        for (int j = 0; j < 4; ++j) {
            FragBc b;
            wmma::load_matrix_sync(b, Bs + (wn * 64 + j * 16) * AST + ks, AST);
#pragma unroll
            for (int i = 0; i < 4; ++i)
                wmma::mma_sync(acc[i][j], a[i], b, acc[i][j]);
        }
    }
}
// warp tile 32x64, NT
__device__ __forceinline__ void mma_col64(FragC acc[2][4], const bf16* As, const bf16* Bs,
                                          int wm, int wn) {
#pragma unroll
    for (int ks = 0; ks < 64; ks += 16) {
        FragA a[2];
        wmma::load_matrix_sync(a[0], As + (wm * 32) * AST + ks,      AST);
        wmma::load_matrix_sync(a[1], As + (wm * 32 + 16) * AST + ks, AST);
#pragma unroll
        for (int j = 0; j < 4; ++j) {
            FragBc b;
            wmma::load_matrix_sync(b, Bs + (wn * 64 + j * 16) * AST + ks, AST);
            wmma::mma_sync(acc[0][j], a[0], b, acc[0][j]);
            wmma::mma_sync(acc[1][j], a[1], b, acc[1][j]);
        }
    }
}
// warp tile 32x64, B row-major (stride BRST)
__device__ __forceinline__ void mma_row64(FragC acc[2][4], const bf16* As, const bf16* Bs,
                                          int wm, int wn) {
#pragma unroll
    for (int ks = 0; ks < 64; ks += 16) {
        FragA a[2];
        wmma::load_matrix_sync(a[0], As + (wm * 32) * AST + ks,      AST);
        wmma::load_matrix_sync(a[1], As + (wm * 32 + 16) * AST + ks, AST);
#pragma unroll
        for (int j = 0; j < 4; ++j) {
            FragBr b;
            wmma::load_matrix_sync(b, Bs + ks * BRST + wn * 64 + j * 16, BRST);
            wmma::mma_sync(acc[0][j], a[0], b, acc[0][j]);
            wmma::mma_sync(acc[1][j], a[1], b, acc[1][j]);
        }
    }
}

// ---------------- epilogues -------------------------------------------------------
__device__ __forceinline__ void stage_acc8(FragC acc[2][4], float* stg, int wm, int wn) {
#pragma unroll
    for (int i = 0; i < 2; ++i)
#pragma unroll
        for (int j = 0; j < 4; ++j)
            wmma::store_matrix_sync(stg + (wm * 32 + i * 16) * EP_STRIDE + wn * 64 + j * 16,
                                    acc[i][j], EP_STRIDE, wmma::mem_row_major);
}

// MODE 0: plain bf16. MODE 1: causal relu/N bf16.
template <int MODE>
__device__ __forceinline__ void ep_bf16(FragC acc[2][4], char* dsm, bf16* C, int ldc,
                                        int q0, int m0, int tid, int wm, int wn) {
    float* stg = reinterpret_cast<float*>(dsm);
    stage_acc8(acc, stg, wm, wn);
    __syncthreads();
    const float inv_n = 1.0f / (float)N_;
#pragma unroll
    for (int it = 0; it < 8; ++it) {
        int idx = it * 256 + tid;
        int r = idx >> 4, cv = idx & 15;
        const float* p = stg + r * EP_STRIDE + cv * 8;
        union { bf16 v[8]; uint4 u4; } pk;
#pragma unroll
        for (int e = 0; e < 8; ++e) {
            float v = p[e];
            if (MODE == 1) {
                int gm = m0 + cv * 8 + e;
                v = (gm <= q0 + r) ? fmaxf(v, 0.0f) * inv_n : 0.0f;
            }
            pk.v[e] = __float2bfloat16(v);
        }
        *reinterpret_cast<uint4*>(C + (size_t)r * ldc + cv * 8) = pk.u4;
    }
    __syncthreads();
}

__device__ __forceinline__ void ep_resid(FragC acc[2][4], char* dsm, float* out,
                                         const float* x, size_t rowbase, int colbase,
                                         int tid, int wm, int wn) {
    float* stg = reinterpret_cast<float*>(dsm);
    stage_acc8(acc, stg, wm, wn);
    __syncthreads();
#pragma unroll
    for (int it = 0; it < 16; ++it) {
        int idx = it * 256 + tid;
        int r = idx >> 5, cv = idx & 31;
        size_t o = (rowbase + r) * (size_t)DV_ + colbase + cv * 4;
        float4 xv = *reinterpret_cast<const float4*>(x + o);
        const float* p = stg + r * EP_STRIDE + cv * 4;
        float4 ov = make_float4(xv.x + p[0], xv.y + p[1], xv.z + p[2], xv.w + p[3]);
        *reinterpret_cast<float4*>(out + o) = ov;
    }
    __syncthreads();
}

// wide epilogue: 128x256 bf16 in two 128-col halves
__device__ __forceinline__ void ep_wide(FragC acc[4][4], char* dsm, bf16* C, int ldc,
                                        int tid, int wm, int wn) {
    float* stg = reinterpret_cast<float*>(dsm);
#pragma unroll
    for (int half = 0; half < 2; ++half) {
        if ((wn >> 1) == half) {
            int cb = (wn & 1) * 64;
#pragma unroll
            for (int i = 0; i < 4; ++i)
#pragma unroll
                for (int j = 0; j < 4; ++j)
                    wmma::store_matrix_sync(stg + (wm * 64 + i * 16) * EP_STRIDE + cb + j * 16,
                                            acc[i][j], EP_STRIDE, wmma::mem_row_major);
        }
        __syncthreads();
#pragma unroll
        for (int it = 0; it < 8; ++it) {
            int idx = it * 256 + tid;
            int r = idx >> 4, cv = idx & 15;
            const float* p = stg + r * EP_STRIDE + cv * 8;
            union { bf16 v[8]; uint4 u4; } pk;
#pragma unroll
            for (int e = 0; e < 8; ++e) pk.v[e] = __float2bfloat16(p[e]);
            *reinterpret_cast<uint4*>(C + (size_t)r * ldc + half * 128 + cv * 8) = pk.u4;
        }
        __syncthreads();
    }
}

// ---------------- kernels ---------------------------------------------------------
__global__ void f2bf_kernel(const float4* __restrict__ in,
                            __nv_bfloat162* __restrict__ out, int n4) {
    int i = blockIdx.x * blockDim.x + threadIdx.x;
    if (i < n4) {
        float4 v = in[i];
        out[2 * i]     = __floats2bfloat162_rn(v.x, v.y);
        out[2 * i + 1] = __floats2bfloat162_rn(v.z, v.w);
    }
}

// projection: C[128 x 256] = A rows * W rows^T, BK=64, 3-stage ring
__global__ __launch_bounds__(256, 1) void k_proj2(const bf16* __restrict__ A0,
                                                  const bf16* __restrict__ W,
                                                  bf16* __restrict__ C0, int ldc) {
    extern __shared__ char dsm[];
    uint32_t sb = smem_u32(dsm);
    int tid = threadIdx.x, wid = tid >> 5;
    int wm = wid & 1, wn = wid >> 1;

    const bf16* A  = A0 + (size_t)blockIdx.y * 128 * D_;
    const bf16* Bp = W  + (size_t)blockIdx.x * 256 * D_;
    bf16* C = C0 + (size_t)(blockIdx.y * 128) * ldc + blockIdx.x * 256;

    FragC acc[4][4];
#pragma unroll
    for (int i = 0; i < 4; ++i)
#pragma unroll
        for (int j = 0; j < 4; ++j) wmma::fill_fragment(acc[i][j], 0.0f);

    const int nk = D_ / 64;  // 16
#pragma unroll
    for (int s = 0; s < 2; ++s) {
        ld_A64 (sb + s * PJ_STAGE,              A  + s * 64, D_, tid);
        ld_B64w(sb + s * PJ_STAGE + PJ_A_BYTES, Bp + s * 64, D_, tid);
        cp_commit();
    }
    for (int i = 0; i < nk; ++i) {
        cp_wait1();
        __syncthreads();
        int ci = i + 2;
        if (ci < nk) {
            uint32_t st = sb + (uint32_t)(ci % 3) * PJ_STAGE;
            ld_A64 (st,              A  + ci * 64, D_, tid);
            ld_B64w(st + PJ_A_BYTES, Bp + ci * 64, D_, tid);
        }
        cp_commit();
        const bf16* As = reinterpret_cast<const bf16*>(dsm + (i % 3) * PJ_STAGE);
        mma_wide(acc, As, As + PJ_A_BYTES / 2, wm, wn);
    }
    cp_wait0();
    __syncthreads();
    ep_wide(acc, dsm, C, ldc, tid, wm, wn);
}

// causal relu(QK^T)/N -> sim (lower-triangle tiles only), BK=64, nk=2
__global__ __launch_bounds__(256, 2) void k_scores(const bf16* __restrict__ Q,
                                                   const bf16* __restrict__ Kx,
                                                   bf16* __restrict__ sim) {
    int mt = blockIdx.x, nt = blockIdx.y;
    if (mt > nt) return;
    int b = blockIdx.z >> 3, h = blockIdx.z & 7;
    extern __shared__ char dsm[];
    uint32_t sb = smem_u32(dsm);
    int tid = threadIdx.x, wid = tid >> 5;
    int wm = wid & 3, wn = wid >> 2;

    const bf16* A  = Q  + ((size_t)(b * N_ + nt * 128)) * HDK + h * DK_;
    const bf16* Bp = Kx + ((size_t)(b * N_ + mt * 128)) * HDK + h * DK_;
    bf16* C = sim + ((size_t)(b * N_ + nt * 128)) * HN + (size_t)h * N_ + mt * 128;

    FragC acc[2][4];
#pragma unroll
    for (int i = 0; i < 2; ++i)
#pragma unroll
        for (int j = 0; j < 4; ++j) wmma::fill_fragment(acc[i][j], 0.0f);

#pragma unroll
    for (int s = 0; s < 2; ++s) {
        ld_A64(sb + s * SC_STAGE,              A  + s * 64, HDK, tid);
        ld_A64(sb + s * SC_STAGE + SC_STAGE/2, Bp + s * 64, HDK, tid);
        cp_commit();
    }
    cp_wait0();
    __syncthreads();
#pragma unroll
    for (int i = 0; i < 2; ++i) {
        const bf16* As = reinterpret_cast<const bf16*>(dsm + i * SC_STAGE);
        mma_col64(acc, As, As + SC_STAGE / 4, wm, wn);
    }
    __syncthreads();
    ep_bf16<1>(acc, dsm, C, HN, nt * 128, mt * 128, tid, wm, wn);
}

// out = x + sim V : per-head K loop with causal bound, BK=64, 3-stage ring
__global__ __launch_bounds__(256, 2) void k_av(const bf16* __restrict__ sim,
                                               const bf16* __restrict__ V,
                                               const float* __restrict__ x,
                                               float* __restrict__ out) {
    int vt = blockIdx.x;
    int tn = 15 - blockIdx.y;        // heavy tiles first
    int b  = blockIdx.z;
    extern __shared__ char dsm[];
    uint32_t sb = smem_u32(dsm);
    int tid = threadIdx.x, wid = tid >> 5;
    int wm = wid & 3, wn = wid >> 2;

    const bf16* Arow = sim + ((size_t)(b * N_ + tn * 128)) * HN;
    const bf16* Vb   = V + (size_t)b * N_ * HDV + vt * 128;

    FragC acc[2][4];
#pragma unroll
    for (int i = 0; i < 2; ++i)
#pragma unroll
        for (int j = 0; j < 4; ++j) wmma::fill_fragment(acc[i][j], 0.0f);

    const int nkh = (tn + 1) * 2;    // K=64 chunks per head
    const int nk  = nkh * H_;
#pragma unroll
    for (int s = 0; s < 2; ++s) {
        // nk >= 16 always
        ld_A64   (sb + s * AV_STAGE,              Arow + s * 64, HN, tid);
        ld_Brow64(sb + s * AV_STAGE + AV_A_BYTES, Vb + (size_t)(s * 64) * HDV, HDV, tid);
        cp_commit();
    }
    for (int i = 0; i < nk; ++i) {
        cp_wait1();
        __syncthreads();
        int ci = i + 2;
        if (ci < nk) {
            int h = ci / nkh, kc = ci - h * nkh;
            uint32_t st = sb + (uint32_t)(ci % 3) * AV_STAGE;
            ld_A64   (st,              Arow + h * N_ + kc * 64, HN, tid);
            ld_Brow64(st + AV_A_BYTES, Vb + (size_t)(kc * 64) * HDV + h * DV_, HDV, tid);
        }
        cp_commit();
        const bf16* As = reinterpret_cast<const bf16*>(dsm + (i % 3) * AV_STAGE);
        mma_row64(acc, As, As + AV_A_BYTES / 2, wm, wn);
    }
    cp_wait0();
    __syncthreads();
    ep_resid(acc, dsm, out, x, (size_t)(b * N_ + tn * 128), vt * 128, tid, wm, wn);
}

// ---------------- host launcher ---------------------------------------------------
static void conv_launch(const float* src, bf16* dst, int n) {
    int n4 = n / 4;
    f2bf_kernel<<<(n4 + 255) / 256, 256>>>(
        reinterpret_cast<const float4*>(src),
        reinterpret_cast<__nv_bfloat162*>(dst), n4);
}

extern "C" void kernel_launch(void* const* d_in, const int* in_sizes, int n_in,
                              void* d_out, int out_size) {
    (void)in_sizes; (void)n_in; (void)out_size;
    const float* x  = (const float*)d_in[0];
    const float* Wq = (const float*)d_in[1];
    const float* Wk = (const float*)d_in[2];
    const float* Wv = (const float*)d_in[3];

    bf16 *xb, *wqb, *wkb, *wvb, *Q, *K, *V, *sim;
    cudaGetSymbolAddress((void**)&xb,  g_xb);
    cudaGetSymbolAddress((void**)&wqb, g_wqb);
    cudaGetSymbolAddress((void**)&wkb, g_wkb);
    cudaGetSymbolAddress((void**)&wvb, g_wvb);
    cudaGetSymbolAddress((void**)&Q,   g_Q);
    cudaGetSymbolAddress((void**)&K,   g_K);
    cudaGetSymbolAddress((void**)&V,   g_V);
    cudaGetSymbolAddress((void**)&sim, g_sim);

    cudaFuncSetAttribute(k_proj2,  cudaFuncAttributeMaxDynamicSharedMemorySize, PJ_DSMEM);
    cudaFuncSetAttribute(k_scores, cudaFuncAttributeMaxDynamicSharedMemorySize, SC_DSMEM);
    cudaFuncSetAttribute(k_av,     cudaFuncAttributeMaxDynamicSharedMemorySize, AV_DSMEM);

    conv_launch(x,  xb,  B_ * N_ * D_);
    conv_launch(Wq, wqb, H_ * DK_ * D_);
    conv_launch(Wk, wkb, H_ * DK_ * D_);
    conv_launch(Wv, wvb, H_ * DV_ * D_);

    // Q = x Wq^T, K = x Wk^T, V = x Wv^T  (CTA tile 128x256)
    k_proj2<<<dim3(HDK / 256, (B_ * N_) / 128), 256, PJ_DSMEM>>>(xb, wqb, Q, HDK);
    k_proj2<<<dim3(HDK / 256, (B_ * N_) / 128), 256, PJ_DSMEM>>>(xb, wkb, K, HDK);
    k_proj2<<<dim3(HDV / 256, (B_ * N_) / 128), 256, PJ_DSMEM>>>(xb, wvb, V, HDV);

    // sim = causal relu(Q K^T)/N  (lower-triangle tiles only)
    k_scores<<<dim3(16, 16, 16), 256, SC_DSMEM>>>(Q, K, sim);

    // out = x + sim V (heavy-first, 256 blocks, 2 CTAs/SM)
    k_av<<<dim3(8, 16, 2), 256, AV_DSMEM>>>(sim, V, x, (float*)d_out);
}

// round 5
// speedup vs baseline: 1.1488x; 1.1488x over previous
#include <cuda_runtime.h>
#include <cuda_bf16.h>
#include <mma.h>
#include <cstdint>

using namespace nvcuda;
using bf16 = __nv_bfloat16;

// ---------------- problem dims --------------------------------------------------
constexpr int B_  = 2;
constexpr int N_  = 2048;
constexpr int D_  = 1024;
constexpr int H_  = 8;
constexpr int DK_ = 128;
constexpr int DV_ = 1024;
constexpr int HDK = H_ * DK_;    // 1024
constexpr int HDV = H_ * DV_;    // 8192
constexpr int HN  = H_ * N_;     // 16384

// ---------------- tiling / smem config -------------------------------------------
constexpr int A_STRIDE = 40;              // K-major stage row stride (elems), BK=32
constexpr int B_ROW_STRIDE = 136;         // row-major B stage row stride (elems)
constexpr int EP_STRIDE = 136;            // fp32 epilogue stage stride

// proj/scores (128x128, BK=32): A 128x40 + B 128x40 per stage
constexpr int STAGE_BYTES = 20480;
constexpr int DSMEM = 4 * STAGE_BYTES;    // 81920 (also fp32 epilogue stage 128x136)

// AV (64x128, BK=32): A 64x40 (5120B) + B 32x136 (8704B)
constexpr int AV_A_BYTES = 64 * A_STRIDE * 2;     // 5120
constexpr int AV_STAGE   = AV_A_BYTES + 32 * B_ROW_STRIDE * 2;  // 13824
constexpr int AV_DSMEM   = 4 * AV_STAGE;          // 55296 (>= 64x136 fp32 = 34816)

// ---------------- scratch (__device__ globals) ----------------------------------
__device__ bf16 g_xb [(size_t)B_ * N_ * D_];
__device__ bf16 g_wqb[(size_t)H_ * DK_ * D_];
__device__ bf16 g_wkb[(size_t)H_ * DK_ * D_];
__device__ bf16 g_wvb[(size_t)H_ * DV_ * D_];
__device__ bf16 g_Q  [(size_t)B_ * N_ * HDK];
__device__ bf16 g_K  [(size_t)B_ * N_ * HDK];
__device__ bf16 g_V  [(size_t)B_ * N_ * HDV];
__device__ bf16 g_sim[(size_t)B_ * N_ * HN];   // lower-triangle tiles only

// ---------------- fragment types -------------------------------------------------
using FragA  = wmma::fragment<wmma::matrix_a, 16, 16, 16, bf16, wmma::row_major>;
using FragBc = wmma::fragment<wmma::matrix_b, 16, 16, 16, bf16, wmma::col_major>;
using FragBr = wmma::fragment<wmma::matrix_b, 16, 16, 16, bf16, wmma::row_major>;
using FragC  = wmma::fragment<wmma::accumulator, 16, 16, 16, float>;

// ---------------- cp.async helpers -----------------------------------------------
__device__ __forceinline__ uint32_t smem_u32(const void* p) {
    uint32_t a;
    asm("{ .reg .u64 t; cvta.to.shared.u64 t, %1; cvt.u32.u64 %0, t; }"
        : "=r"(a) : "l"(p));
    return a;
}
__device__ __forceinline__ void cp16(uint32_t dst, const void* src) {
    asm volatile("cp.async.cg.shared.global [%0], [%1], 16;"
                 :: "r"(dst), "l"(__cvta_generic_to_global(src)));
}
__device__ __forceinline__ void cp_commit() {
    asm volatile("cp.async.commit_group;" ::: "memory");
}
__device__ __forceinline__ void cp_wait2() {
    asm volatile("cp.async.wait_group 2;" ::: "memory");
}

// 128 rows x 32 cols K-major (row stride 40 elems)
__device__ __forceinline__ void ld_A(uint32_t sdst, const bf16* g, int ld, int tid) {
#pragma unroll
    for (int i = 0; i < 2; ++i) {
        int u = tid + i * 256;
        int r = u >> 2, c = (u & 3) * 8;
        cp16(sdst + (uint32_t)(r * (A_STRIDE * 2) + c * 2), g + (size_t)r * ld + c);
    }
}
// 64 rows x 32 cols K-major (row stride 40 elems) — one cp16 per thread
__device__ __forceinline__ void ld_A64r(uint32_t sdst, const bf16* g, int ld, int tid) {
    int r = tid >> 2, c = (tid & 3) * 8;
    cp16(sdst + (uint32_t)(r * (A_STRIDE * 2) + c * 2), g + (size_t)r * ld + c);
}
// 32 rows(k) x 128 cols(n) row-major (row stride 136 elems)
__device__ __forceinline__ void ld_Brow(uint32_t sdst, const bf16* g, int ld, int tid) {
#pragma unroll
    for (int i = 0; i < 2; ++i) {
        int u = tid + i * 256;
        int r = u >> 4, c = (u & 15) * 8;
        cp16(sdst + (uint32_t)(r * (B_ROW_STRIDE * 2) + c * 2), g + (size_t)r * ld + c);
    }
}

// ---------------- MMA micro-steps -------------------------------------------------
// warp tile 32x64, NT (B col-major view, stride 40)
__device__ __forceinline__ void mma_col(FragC acc[2][4], const bf16* As, const bf16* Bs,
                                        int wm, int wn) {
#pragma unroll
    for (int ks = 0; ks < 32; ks += 16) {
        FragA a[2];
        wmma::load_matrix_sync(a[0], As + (wm * 32) * A_STRIDE + ks,      A_STRIDE);
        wmma::load_matrix_sync(a[1], As + (wm * 32 + 16) * A_STRIDE + ks, A_STRIDE);
#pragma unroll
        for (int j = 0; j < 4; ++j) {
            FragBc b;
            wmma::load_matrix_sync(b, Bs + (wn * 64 + j * 16) * A_STRIDE + ks, A_STRIDE);
            wmma::mma_sync(acc[0][j], a[0], b, acc[0][j]);
            wmma::mma_sync(acc[1][j], a[1], b, acc[1][j]);
        }
    }
}
// warp tile 32x32, B row-major (stride 136) — for AV64
__device__ __forceinline__ void mma_row32(FragC acc[2][2], const bf16* As, const bf16* Bs,
                                          int wm, int wn) {
#pragma unroll
    for (int ks = 0; ks < 32; ks += 16) {
        FragA a[2];
        wmma::load_matrix_sync(a[0], As + (wm * 32) * A_STRIDE + ks,      A_STRIDE);
        wmma::load_matrix_sync(a[1], As + (wm * 32 + 16) * A_STRIDE + ks, A_STRIDE);
#pragma unroll
        for (int j = 0; j < 2; ++j) {
            FragBr b;
            wmma::load_matrix_sync(b, Bs + ks * B_ROW_STRIDE + wn * 32 + j * 16, B_ROW_STRIDE);
            wmma::mma_sync(acc[0][j], a[0], b, acc[0][j]);
            wmma::mma_sync(acc[1][j], a[1], b, acc[1][j]);
        }
    }
}

// ---------------- pipelined NT mainloop (128x128) ----------------------------------
__device__ __forceinline__ void loop_nt(FragC acc[2][4], char* dsm,
                                        const bf16* A, int lda,
                                        const bf16* Bp, int ldb,
                                        int nk, int tid, int wm, int wn) {
    uint32_t sb = smem_u32(dsm);
#pragma unroll
    for (int s = 0; s < 3; ++s) {
        if (s < nk) {
            ld_A(sb + s * STAGE_BYTES,         A  + s * 32, lda, tid);
            ld_A(sb + s * STAGE_BYTES + 10240, Bp + s * 32, ldb, tid);
        }
        cp_commit();
    }
    for (int i = 0; i < nk; ++i) {
        cp_wait2();
        __syncthreads();
        int ci = i + 3;
        if (ci < nk) {
            uint32_t st = sb + (uint32_t)(ci & 3) * STAGE_BYTES;
            ld_A(st,         A  + ci * 32, lda, tid);
            ld_A(st + 10240, Bp + ci * 32, ldb, tid);
        }
        cp_commit();
        const bf16* As = reinterpret_cast<const bf16*>(dsm + (i & 3) * STAGE_BYTES);
        mma_col(acc, As, As + 10240 / 2, wm, wn);
    }
    __syncthreads();
}

// ---------------- epilogues -------------------------------------------------------
__device__ __forceinline__ void stage_acc8(FragC acc[2][4], float* stg, int wm, int wn) {
#pragma unroll
    for (int i = 0; i < 2; ++i)
#pragma unroll
        for (int j = 0; j < 4; ++j)
            wmma::store_matrix_sync(stg + (wm * 32 + i * 16) * EP_STRIDE + wn * 64 + j * 16,
                                    acc[i][j], EP_STRIDE, wmma::mem_row_major);
}

// MODE 0: plain bf16. MODE 1: causal relu/N bf16.
template <int MODE>
__device__ __forceinline__ void ep_bf16(FragC acc[2][4], char* dsm, bf16* C, int ldc,
                                        int q0, int m0, int tid, int wm, int wn) {
    float* stg = reinterpret_cast<float*>(dsm);
    stage_acc8(acc, stg, wm, wn);
    __syncthreads();
    const float inv_n = 1.0f / (float)N_;
#pragma unroll
    for (int it = 0; it < 8; ++it) {
        int idx = it * 256 + tid;
        int r = idx >> 4, cv = idx & 15;
        const float* p = stg + r * EP_STRIDE + cv * 8;
        union { bf16 v[8]; uint4 u4; } pk;
#pragma unroll
        for (int e = 0; e < 8; ++e) {
            float v = p[e];
            if (MODE == 1) {
                int gm = m0 + cv * 8 + e;
                v = (gm <= q0 + r) ? fmaxf(v, 0.0f) * inv_n : 0.0f;
            }
            pk.v[e] = __float2bfloat16(v);
        }
        *reinterpret_cast<uint4*>(C + (size_t)r * ldc + cv * 8) = pk.u4;
    }
    __syncthreads();
}

// ---------------- kernels ---------------------------------------------------------
__global__ void f2bf_kernel(const float4* __restrict__ in,
                            __nv_bfloat162* __restrict__ out, int n4) {
    int i = blockIdx.x * blockDim.x + threadIdx.x;
    if (i < n4) {
        float4 v = in[i];
        out[2 * i]     = __floats2bfloat162_rn(v.x, v.y);
        out[2 * i + 1] = __floats2bfloat162_rn(v.z, v.w);
    }
}

__global__ __launch_bounds__(256, 2) void k_proj(const bf16* __restrict__ A0,
                                                 const bf16* __restrict__ W,
                                                 bf16* __restrict__ C0, int ldc) {
    extern __shared__ char dsm[];
    int tid = threadIdx.x, wid = tid >> 5;
    int wm = wid & 3, wn = wid >> 2;
    const bf16* A  = A0 + (size_t)blockIdx.y * 128 * D_;
    const bf16* Bp = W  + (size_t)blockIdx.x * 128 * D_;
    bf16* C = C0 + (size_t)(blockIdx.y * 128) * ldc + blockIdx.x * 128;

    FragC acc[2][4];
#pragma unroll
    for (int i = 0; i < 2; ++i)
#pragma unroll
        for (int j = 0; j < 4; ++j) wmma::fill_fragment(acc[i][j], 0.0f);

    loop_nt(acc, dsm, A, D_, Bp, D_, D_ / 32, tid, wm, wn);
    ep_bf16<0>(acc, dsm, C, ldc, 0, 0, tid, wm, wn);
}

__global__ __launch_bounds__(256, 2) void k_scores(const bf16* __restrict__ Q,
                                                   const bf16* __restrict__ Kx,
                                                   bf16* __restrict__ sim) {
    int mt = blockIdx.x, nt = blockIdx.y;
    if (mt > nt) return;                       // upper tiles never read by AV
    int b = blockIdx.z >> 3, h = blockIdx.z & 7;
    extern __shared__ char dsm[];
    int tid = threadIdx.x, wid = tid >> 5;
    int wm = wid & 3, wn = wid >> 2;

    const bf16* A  = Q  + ((size_t)(b * N_ + nt * 128)) * HDK + h * DK_;
    const bf16* Bp = Kx + ((size_t)(b * N_ + mt * 128)) * HDK + h * DK_;
    bf16* C = sim + ((size_t)(b * N_ + nt * 128)) * HN + (size_t)h * N_ + mt * 128;

    FragC acc[2][4];
#pragma unroll
    for (int i = 0; i < 2; ++i)
#pragma unroll
        for (int j = 0; j < 4; ++j) wmma::fill_fragment(acc[i][j], 0.0f);

    loop_nt(acc, dsm, A, HDK, Bp, HDK, DK_ / 32, tid, wm, wn);
    ep_bf16<1>(acc, dsm, C, HN, nt * 128, mt * 128, tid, wm, wn);
}

// AV with 64-row tiles: 32 tiles paired (p, 31-p) -> 256 uniform blocks of 17 units.
__global__ __launch_bounds__(256, 2) void k_av64(const bf16* __restrict__ sim,
                                                 const bf16* __restrict__ V,
                                                 const float* __restrict__ x,
                                                 float* __restrict__ out) {
    int vt = blockIdx.x, pair = blockIdx.y, b = blockIdx.z;
    extern __shared__ char dsm[];
    uint32_t sb = smem_u32(dsm);
    int tid = threadIdx.x, wid = tid >> 5;
    int wm = wid & 1, wn = wid >> 1;     // 2 x 4 warps, warp tile 32x32

    const bf16* Vb = V + (size_t)b * N_ * HDV + vt * 128;
    int tiles2[2] = {31 - pair, pair};   // heavy tile first

#pragma unroll
    for (int t = 0; t < 2; ++t) {
        int t64 = tiles2[t];
        const bf16* Arow = sim + ((size_t)(b * N_ + t64 * 64)) * HN;
        const int nkh = (t64 + 1) * 2;   // 32-wide chunks per head (causal bound)
        const int nk  = nkh * H_;        // >= 16

        FragC acc[2][2];
#pragma unroll
        for (int i = 0; i < 2; ++i)
#pragma unroll
            for (int j = 0; j < 2; ++j) wmma::fill_fragment(acc[i][j], 0.0f);

#pragma unroll
        for (int s = 0; s < 3; ++s) {
            int h = s / nkh, kc = s - h * nkh;
            ld_A64r(sb + s * AV_STAGE, Arow + h * N_ + kc * 32, HN, tid);
            ld_Brow(sb + s * AV_STAGE + AV_A_BYTES,
                    Vb + (size_t)(kc * 32) * HDV + h * DV_, HDV, tid);
            cp_commit();
        }
        for (int i = 0; i < nk; ++i) {
            cp_wait2();
            __syncthreads();
            int ci = i + 3;
            if (ci < nk) {
                int h = ci / nkh, kc = ci - h * nkh;
                uint32_t st = sb + (uint32_t)(ci & 3) * AV_STAGE;
                ld_A64r(st, Arow + h * N_ + kc * 32, HN, tid);
                ld_Brow(st + AV_A_BYTES, Vb + (size_t)(kc * 32) * HDV + h * DV_, HDV, tid);
            }
            cp_commit();
            const bf16* As = reinterpret_cast<const bf16*>(dsm + (i & 3) * AV_STAGE);
            mma_row32(acc, As, As + AV_A_BYTES / 2, wm, wn);
        }
        __syncthreads();

        // epilogue: stage 64x136 fp32, residual add, float4 stores
        float* stg = reinterpret_cast<float*>(dsm);
#pragma unroll
        for (int i = 0; i < 2; ++i)
#pragma unroll
            for (int j = 0; j < 2; ++j)
                wmma::store_matrix_sync(stg + (wm * 32 + i * 16) * EP_STRIDE + wn * 32 + j * 16,
                                        acc[i][j], EP_STRIDE, wmma::mem_row_major);
        __syncthreads();
        size_t rowbase = (size_t)(b * N_ + t64 * 64);
#pragma unroll
        for (int it = 0; it < 8; ++it) {
            int idx = it * 256 + tid;
            int r = idx >> 5, cv = idx & 31;
            size_t o = (rowbase + r) * (size_t)DV_ + vt * 128 + cv * 4;
            float4 xv = *reinterpret_cast<const float4*>(x + o);
            const float* p = stg + r * EP_STRIDE + cv * 4;
            float4 ov = make_float4(xv.x + p[0], xv.y + p[1], xv.z + p[2], xv.w + p[3]);
            *reinterpret_cast<float4*>(out + o) = ov;
        }
        __syncthreads();
    }
}

// ---------------- host launcher ---------------------------------------------------
static void conv_launch(const float* src, bf16* dst, int n) {
    int n4 = n / 4;
    f2bf_kernel<<<(n4 + 255) / 256, 256>>>(
        reinterpret_cast<const float4*>(src),
        reinterpret_cast<__nv_bfloat162*>(dst), n4);
}

extern "C" void kernel_launch(void* const* d_in, const int* in_sizes, int n_in,
                              void* d_out, int out_size) {
    (void)in_sizes; (void)n_in; (void)out_size;
    const float* x  = (const float*)d_in[0];
    const float* Wq = (const float*)d_in[1];
    const float* Wk = (const float*)d_in[2];
    const float* Wv = (const float*)d_in[3];

    bf16 *xb, *wqb, *wkb, *wvb, *Q, *K, *V, *sim;
    cudaGetSymbolAddress((void**)&xb,  g_xb);
    cudaGetSymbolAddress((void**)&wqb, g_wqb);
    cudaGetSymbolAddress((void**)&wkb, g_wkb);
    cudaGetSymbolAddress((void**)&wvb, g_wvb);
    cudaGetSymbolAddress((void**)&Q,   g_Q);
    cudaGetSymbolAddress((void**)&K,   g_K);
    cudaGetSymbolAddress((void**)&V,   g_V);
    cudaGetSymbolAddress((void**)&sim, g_sim);

    cudaFuncSetAttribute(k_proj,   cudaFuncAttributeMaxDynamicSharedMemorySize, DSMEM);
    cudaFuncSetAttribute(k_scores, cudaFuncAttributeMaxDynamicSharedMemorySize, DSMEM);
    cudaFuncSetAttribute(k_av64,   cudaFuncAttributeMaxDynamicSharedMemorySize, AV_DSMEM);

    conv_launch(x,  xb,  B_ * N_ * D_);
    conv_launch(Wq, wqb, H_ * DK_ * D_);
    conv_launch(Wk, wkb, H_ * DK_ * D_);
    conv_launch(Wv, wvb, H_ * DV_ * D_);

    // Q = x Wq^T, K = x Wk^T, V = x Wv^T
    k_proj<<<dim3(HDK / 128, (B_ * N_) / 128), 256, DSMEM>>>(xb, wqb, Q, HDK);
    k_proj<<<dim3(HDK / 128, (B_ * N_) / 128), 256, DSMEM>>>(xb, wkb, K, HDK);
    k_proj<<<dim3(HDV / 128, (B_ * N_) / 128), 256, DSMEM>>>(xb, wvb, V, HDV);

    // sim = causal relu(Q K^T)/N  (lower-triangle tiles only)
    k_scores<<<dim3(16, 16, 16), 256, DSMEM>>>(Q, K, sim);

    // out = x + sim V  (256 uniform paired blocks)
    k_av64<<<dim3(8, 16, 2), 256, AV_DSMEM>>>(sim, V, x, (float*)d_out);
}

// round 6
// speedup vs baseline: 1.2188x; 1.0609x over previous
#include <cuda_runtime.h>
#include <cuda_bf16.h>
#include <mma.h>
#include <cstdint>

using namespace nvcuda;
using bf16 = __nv_bfloat16;

// ---------------- problem dims --------------------------------------------------
constexpr int B_  = 2;
constexpr int N_  = 2048;
constexpr int D_  = 1024;
constexpr int H_  = 8;
constexpr int DK_ = 128;
constexpr int DV_ = 1024;
constexpr int HDK = H_ * DK_;    // 1024
constexpr int HDV = H_ * DV_;    // 8192
constexpr int HN  = H_ * N_;     // 16384

// ---------------- tiling / smem config -------------------------------------------
constexpr int A_STRIDE = 40;              // K-major stage row stride (elems), BK=32
constexpr int B_ROW_STRIDE = 136;         // row-major B stage row stride (elems)
constexpr int EP_STRIDE = 136;            // fp32 epilogue stage stride

// NT kernels (128x128, BK=32): A 128x40 + B 128x40 per stage
constexpr int STAGE_BYTES = 20480;
constexpr int DSMEM = 4 * STAGE_BYTES;    // 81920 (>= 128x136 fp32 epilogue stage)

// AV (128x128, BK=32): A 128x40 (10240B) + B 32x136 (8704B)
constexpr int AV_A_BYTES = 128 * A_STRIDE * 2;                  // 10240
constexpr int AV_STAGE   = AV_A_BYTES + 32 * B_ROW_STRIDE * 2;  // 18944
constexpr int AV_DSMEM   = 4 * AV_STAGE;                        // 75776 (>= 69632 ep)

// ---------------- scratch (__device__ globals) ----------------------------------
__device__ bf16 g_xb [(size_t)B_ * N_ * D_];
__device__ bf16 g_wqb[(size_t)H_ * DK_ * D_];
__device__ bf16 g_wkb[(size_t)H_ * DK_ * D_];
__device__ bf16 g_wvb[(size_t)H_ * DV_ * D_];
__device__ bf16 g_Q  [(size_t)B_ * N_ * HDK];
__device__ bf16 g_K  [(size_t)B_ * N_ * HDK];
__device__ bf16 g_V  [(size_t)B_ * N_ * HDV];
__device__ bf16 g_sim[(size_t)B_ * N_ * HN];   // lower-triangle tiles only

// ---------------- fragment types -------------------------------------------------
using FragA  = wmma::fragment<wmma::matrix_a, 16, 16, 16, bf16, wmma::row_major>;
using FragBc = wmma::fragment<wmma::matrix_b, 16, 16, 16, bf16, wmma::col_major>;
using FragBr = wmma::fragment<wmma::matrix_b, 16, 16, 16, bf16, wmma::row_major>;
using FragC  = wmma::fragment<wmma::accumulator, 16, 16, 16, float>;

// ---------------- cp.async helpers -----------------------------------------------
__device__ __forceinline__ uint32_t smem_u32(const void* p) {
    uint32_t a;
    asm("{ .reg .u64 t; cvta.to.shared.u64 t, %1; cvt.u32.u64 %0, t; }"
        : "=r"(a) : "l"(p));
    return a;
}
__device__ __forceinline__ void cp16(uint32_t dst, const void* src) {
    asm volatile("cp.async.cg.shared.global [%0], [%1], 16;"
                 :: "r"(dst), "l"(__cvta_generic_to_global(src)));
}
__device__ __forceinline__ void cp_commit() {
    asm volatile("cp.async.commit_group;" ::: "memory");
}
__device__ __forceinline__ void cp_wait2() {
    asm volatile("cp.async.wait_group 2;" ::: "memory");
}

// 128 rows x 32 cols K-major (row stride 40 elems), 128 threads, 4 cp16 each
__device__ __forceinline__ void ld_A(uint32_t sdst, const bf16* g, int ld, int tid) {
#pragma unroll
    for (int i = 0; i < 4; ++i) {
        int u = tid + i * 128;
        int r = u >> 2, c = (u & 3) * 8;
        cp16(sdst + (uint32_t)(r * (A_STRIDE * 2) + c * 2), g + (size_t)r * ld + c);
    }
}
// 32 rows(k) x 128 cols(n) row-major (row stride 136 elems), 128 threads
__device__ __forceinline__ void ld_Brow(uint32_t sdst, const bf16* g, int ld, int tid) {
#pragma unroll
    for (int i = 0; i < 4; ++i) {
        int u = tid + i * 128;
        int r = u >> 4, c = (u & 15) * 8;
        cp16(sdst + (uint32_t)(r * (B_ROW_STRIDE * 2) + c * 2), g + (size_t)r * ld + c);
    }
}

// ---------------- MMA micro-steps: warp tile 64x64 --------------------------------
// NT (B col-major view, stride 40)
__device__ __forceinline__ void mma_w64(FragC acc[4][4], const bf16* As, const bf16* Bs,
                                        int wm, int wn) {
#pragma unroll
    for (int ks = 0; ks < 32; ks += 16) {
        FragA a[4];
#pragma unroll
        for (int i = 0; i < 4; ++i)
            wmma::load_matrix_sync(a[i], As + (wm * 64 + i * 16) * A_STRIDE + ks, A_STRIDE);
#pragma unroll
        for (int j = 0; j < 4; ++j) {
            FragBc b;
            wmma::load_matrix_sync(b, Bs + (wn * 64 + j * 16) * A_STRIDE + ks, A_STRIDE);
#pragma unroll
            for (int i = 0; i < 4; ++i)
                wmma::mma_sync(acc[i][j], a[i], b, acc[i][j]);
        }
    }
}
// B row-major (stride 136)
__device__ __forceinline__ void mma_w64r(FragC acc[4][4], const bf16* As, const bf16* Bs,
                                         int wm, int wn) {
#pragma unroll
    for (int ks = 0; ks < 32; ks += 16) {
        FragA a[4];
#pragma unroll
        for (int i = 0; i < 4; ++i)
            wmma::load_matrix_sync(a[i], As + (wm * 64 + i * 16) * A_STRIDE + ks, A_STRIDE);
#pragma unroll
        for (int j = 0; j < 4; ++j) {
            FragBr b;
            wmma::load_matrix_sync(b, Bs + ks * B_ROW_STRIDE + wn * 64 + j * 16, B_ROW_STRIDE);
#pragma unroll
            for (int i = 0; i < 4; ++i)
                wmma::mma_sync(acc[i][j], a[i], b, acc[i][j]);
        }
    }
}

// ---------------- pipelined NT mainloop (128x128, 128 threads) ---------------------
__device__ __forceinline__ void loop_nt(FragC acc[4][4], char* dsm,
                                        const bf16* A, int lda,
                                        const bf16* Bp, int ldb,
                                        int nk, int tid, int wm, int wn) {
    uint32_t sb = smem_u32(dsm);
#pragma unroll
    for (int s = 0; s < 3; ++s) {
        if (s < nk) {
            ld_A(sb + s * STAGE_BYTES,         A  + s * 32, lda, tid);
            ld_A(sb + s * STAGE_BYTES + 10240, Bp + s * 32, ldb, tid);
        }
        cp_commit();
    }
    for (int i = 0; i < nk; ++i) {
        cp_wait2();
        __syncthreads();
        int ci = i + 3;
        if (ci < nk) {
            uint32_t st = sb + (uint32_t)(ci & 3) * STAGE_BYTES;
            ld_A(st,         A  + ci * 32, lda, tid);
            ld_A(st + 10240, Bp + ci * 32, ldb, tid);
        }
        cp_commit();
        const bf16* As = reinterpret_cast<const bf16*>(dsm + (i & 3) * STAGE_BYTES);
        mma_w64(acc, As, As + 10240 / 2, wm, wn);
    }
    __syncthreads();
}

// ---------------- epilogues (128 threads) ------------------------------------------
__device__ __forceinline__ void stage_acc16(FragC acc[4][4], float* stg, int wm, int wn) {
#pragma unroll
    for (int i = 0; i < 4; ++i)
#pragma unroll
        for (int j = 0; j < 4; ++j)
            wmma::store_matrix_sync(stg + (wm * 64 + i * 16) * EP_STRIDE + wn * 64 + j * 16,
                                    acc[i][j], EP_STRIDE, wmma::mem_row_major);
}

// MODE 0: plain bf16. MODE 1: causal relu/N bf16.
template <int MODE>
__device__ __forceinline__ void ep_bf16(FragC acc[4][4], char* dsm, bf16* C, int ldc,
                                        int q0, int m0, int tid, int wm, int wn) {
    float* stg = reinterpret_cast<float*>(dsm);
    stage_acc16(acc, stg, wm, wn);
    __syncthreads();
    const float inv_n = 1.0f / (float)N_;
#pragma unroll
    for (int it = 0; it < 16; ++it) {
        int idx = it * 128 + tid;
        int r = idx >> 4, cv = idx & 15;
        const float* p = stg + r * EP_STRIDE + cv * 8;
        union { bf16 v[8]; uint4 u4; } pk;
#pragma unroll
        for (int e = 0; e < 8; ++e) {
            float v = p[e];
            if (MODE == 1) {
                int gm = m0 + cv * 8 + e;
                v = (gm <= q0 + r) ? fmaxf(v, 0.0f) * inv_n : 0.0f;
            }
            pk.v[e] = __float2bfloat16(v);
        }
        *reinterpret_cast<uint4*>(C + (size_t)r * ldc + cv * 8) = pk.u4;
    }
    __syncthreads();
}

__device__ __forceinline__ void ep_resid(FragC acc[4][4], char* dsm, float* out,
                                         const float* x, size_t rowbase, int colbase,
                                         int tid, int wm, int wn) {
    float* stg = reinterpret_cast<float*>(dsm);
    stage_acc16(acc, stg, wm, wn);
    __syncthreads();
#pragma unroll
    for (int it = 0; it < 32; ++it) {
        int idx = it * 128 + tid;
        int r = idx >> 5, cv = idx & 31;
        size_t o = (rowbase + r) * (size_t)DV_ + colbase + cv * 4;
        float4 xv = *reinterpret_cast<const float4*>(x + o);
        const float* p = stg + r * EP_STRIDE + cv * 4;
        float4 ov = make_float4(xv.x + p[0], xv.y + p[1], xv.z + p[2], xv.w + p[3]);
        *reinterpret_cast<float4*>(out + o) = ov;
    }
    __syncthreads();
}

// ---------------- kernels ---------------------------------------------------------
__global__ void f2bf_kernel(const float4* __restrict__ in,
                            __nv_bfloat162* __restrict__ out, int n4) {
    int i = blockIdx.x * blockDim.x + threadIdx.x;
    if (i < n4) {
        float4 v = in[i];
        out[2 * i]     = __floats2bfloat162_rn(v.x, v.y);
        out[2 * i + 1] = __floats2bfloat162_rn(v.z, v.w);
    }
}

__global__ __launch_bounds__(128) void k_proj(const bf16* __restrict__ A0,
                                              const bf16* __restrict__ W,
                                              bf16* __restrict__ C0, int ldc) {
    extern __shared__ char dsm[];
    int tid = threadIdx.x, wid = tid >> 5;
    int wm = wid & 1, wn = wid >> 1;
    const bf16* A  = A0 + (size_t)blockIdx.y * 128 * D_;
    const bf16* Bp = W  + (size_t)blockIdx.x * 128 * D_;
    bf16* C = C0 + (size_t)(blockIdx.y * 128) * ldc + blockIdx.x * 128;

    FragC acc[4][4];
#pragma unroll
    for (int i = 0; i < 4; ++i)
#pragma unroll
        for (int j = 0; j < 4; ++j) wmma::fill_fragment(acc[i][j], 0.0f);

    loop_nt(acc, dsm, A, D_, Bp, D_, D_ / 32, tid, wm, wn);
    ep_bf16<0>(acc, dsm, C, ldc, 0, 0, tid, wm, wn);
}

__global__ __launch_bounds__(128) void k_scores(const bf16* __restrict__ Q,
                                                const bf16* __restrict__ Kx,
                                                bf16* __restrict__ sim) {
    int mt = blockIdx.x, nt = blockIdx.y;
    if (mt > nt) return;                       // upper tiles never read by AV
    int b = blockIdx.z >> 3, h = blockIdx.z & 7;
    extern __shared__ char dsm[];
    int tid = threadIdx.x, wid = tid >> 5;
    int wm = wid & 1, wn = wid >> 1;

    const bf16* A  = Q  + ((size_t)(b * N_ + nt * 128)) * HDK + h * DK_;
    const bf16* Bp = Kx + ((size_t)(b * N_ + mt * 128)) * HDK + h * DK_;
    bf16* C = sim + ((size_t)(b * N_ + nt * 128)) * HN + (size_t)h * N_ + mt * 128;

    FragC acc[4][4];
#pragma unroll
    for (int i = 0; i < 4; ++i)
#pragma unroll
        for (int j = 0; j < 4; ++j) wmma::fill_fragment(acc[i][j], 0.0f);

    loop_nt(acc, dsm, A, HDK, Bp, HDK, DK_ / 32, tid, wm, wn);
    ep_bf16<1>(acc, dsm, C, HN, nt * 128, mt * 128, tid, wm, wn);
}

// AV: 128-row tiles paired (tn, 15-tn) -> 128 uniform blocks of 68 chunks each.
__global__ __launch_bounds__(128) void k_av(const bf16* __restrict__ sim,
                                            const bf16* __restrict__ V,
                                            const float* __restrict__ x,
                                            float* __restrict__ out) {
    int vt = blockIdx.x, pair = blockIdx.y, b = blockIdx.z;
    extern __shared__ char dsm[];
    uint32_t sb = smem_u32(dsm);
    int tid = threadIdx.x, wid = tid >> 5;
    int wm = wid & 1, wn = wid >> 1;

    const bf16* Vb = V + (size_t)b * N_ * HDV + vt * 128;
    int tiles2[2] = {15 - pair, pair};   // heavy tile first

#pragma unroll
    for (int t = 0; t < 2; ++t) {
        int tn = tiles2[t];
        const bf16* Arow = sim + ((size_t)(b * N_ + tn * 128)) * HN;
        const int nkh = (tn + 1) * 4;    // K=32 chunks per head (causal bound)
        const int nk  = nkh * H_;        // >= 32

        FragC acc[4][4];
#pragma unroll
        for (int i = 0; i < 4; ++i)
#pragma unroll
            for (int j = 0; j < 4; ++j) wmma::fill_fragment(acc[i][j], 0.0f);

#pragma unroll
        for (int s = 0; s < 3; ++s) {
            int h = s / nkh, kc = s - h * nkh;
            ld_A   (sb + s * AV_STAGE, Arow + h * N_ + kc * 32, HN, tid);
            ld_Brow(sb + s * AV_STAGE + AV_A_BYTES,
                    Vb + (size_t)(kc * 32) * HDV + h * DV_, HDV, tid);
            cp_commit();
        }
        for (int i = 0; i < nk; ++i) {
            cp_wait2();
            __syncthreads();
            int ci = i + 3;
            if (ci < nk) {
                int h = ci / nkh, kc = ci - h * nkh;
                uint32_t st = sb + (uint32_t)(ci & 3) * AV_STAGE;
                ld_A   (st, Arow + h * N_ + kc * 32, HN, tid);
                ld_Brow(st + AV_A_BYTES, Vb + (size_t)(kc * 32) * HDV + h * DV_, HDV, tid);
            }
            cp_commit();
            const bf16* As = reinterpret_cast<const bf16*>(dsm + (i & 3) * AV_STAGE);
            mma_w64r(acc, As, As + AV_A_BYTES / 2, wm, wn);
        }
        __syncthreads();
        ep_resid(acc, dsm, out, x, (size_t)(b * N_ + tn * 128), vt * 128, tid, wm, wn);
    }
}

// ---------------- host launcher ---------------------------------------------------
static void conv_launch(const float* src, bf16* dst, int n) {
    int n4 = n / 4;
    f2bf_kernel<<<(n4 + 255) / 256, 256>>>(
        reinterpret_cast<const float4*>(src),
        reinterpret_cast<__nv_bfloat162*>(dst), n4);
}

extern "C" void kernel_launch(void* const* d_in, const int* in_sizes, int n_in,
                              void* d_out, int out_size) {
    (void)in_sizes; (void)n_in; (void)out_size;
    const float* x  = (const float*)d_in[0];
    const float* Wq = (const float*)d_in[1];
    const float* Wk = (const float*)d_in[2];
    const float* Wv = (const float*)d_in[3];

    bf16 *xb, *wqb, *wkb, *wvb, *Q, *K, *V, *sim;
    cudaGetSymbolAddress((void**)&xb,  g_xb);
    cudaGetSymbolAddress((void**)&wqb, g_wqb);
    cudaGetSymbolAddress((void**)&wkb, g_wkb);
    cudaGetSymbolAddress((void**)&wvb, g_wvb);
    cudaGetSymbolAddress((void**)&Q,   g_Q);
    cudaGetSymbolAddress((void**)&K,   g_K);
    cudaGetSymbolAddress((void**)&V,   g_V);
    cudaGetSymbolAddress((void**)&sim, g_sim);

    cudaFuncSetAttribute(k_proj,   cudaFuncAttributeMaxDynamicSharedMemorySize, DSMEM);
    cudaFuncSetAttribute(k_scores, cudaFuncAttributeMaxDynamicSharedMemorySize, DSMEM);
    cudaFuncSetAttribute(k_av,     cudaFuncAttributeMaxDynamicSharedMemorySize, AV_DSMEM);

    conv_launch(x,  xb,  B_ * N_ * D_);
    conv_launch(Wq, wqb, H_ * DK_ * D_);
    conv_launch(Wk, wkb, H_ * DK_ * D_);
    conv_launch(Wv, wvb, H_ * DV_ * D_);

    // Q = x Wq^T, K = x Wk^T, V = x Wv^T
    k_proj<<<dim3(HDK / 128, (B_ * N_) / 128), 128, DSMEM>>>(xb, wqb, Q, HDK);
    k_proj<<<dim3(HDK / 128, (B_ * N_) / 128), 128, DSMEM>>>(xb, wkb, K, HDK);
    k_proj<<<dim3(HDV / 128, (B_ * N_) / 128), 128, DSMEM>>>(xb, wvb, V, HDV);

    // sim = causal relu(Q K^T)/N  (lower-triangle tiles only)
    k_scores<<<dim3(16, 16, 16), 128, DSMEM>>>(Q, K, sim);

    // out = x + sim V  (128 uniform paired blocks)
    k_av<<<dim3(8, 8, 2), 128, AV_DSMEM>>>(sim, V, x, (float*)d_out);
}

// round 7
// speedup vs baseline: 1.3316x; 1.0925x over previous
#include <cuda_runtime.h>
#include <cuda_bf16.h>
#include <mma.h>
#include <cstdint>

using namespace nvcuda;
using bf16 = __nv_bfloat16;

// ---------------- problem dims --------------------------------------------------
constexpr int B_  = 2;
constexpr int N_  = 2048;
constexpr int D_  = 1024;
constexpr int H_  = 8;
constexpr int DK_ = 128;
constexpr int DV_ = 1024;
constexpr int HDK = H_ * DK_;    // 1024
constexpr int HDV = H_ * DV_;    // 8192
constexpr int HN  = H_ * N_;     // 16384

// ---------------- tiling / smem config -------------------------------------------
constexpr int A_STRIDE = 40;              // K-major stage row stride (elems), BK=32
constexpr int B_ROW_STRIDE = 136;         // row-major B stage row stride (elems)
constexpr int EP_STRIDE = 136;            // fp32 epilogue stage stride

// NT kernels (128x128, BK=32): A 128x40 + B 128x40 per stage
constexpr int STAGE_BYTES = 20480;
constexpr int DSMEM = 4 * STAGE_BYTES;    // 81920 (>= 128x136 fp32 epilogue stage)

// AV (64x128, BK=32): A 64x40 (5120B) + B 32x136 (8704B)
constexpr int AV_A_BYTES = 64 * A_STRIDE * 2;                   // 5120
constexpr int AV_STAGE   = AV_A_BYTES + 32 * B_ROW_STRIDE * 2;  // 13824
constexpr int AV_DSMEM   = 4 * AV_STAGE;                        // 55296 (>= 64x136 fp32)

// ---------------- scratch (__device__ globals) ----------------------------------
__device__ bf16 g_xb [(size_t)B_ * N_ * D_];
__device__ bf16 g_wqb[(size_t)H_ * DK_ * D_];
__device__ bf16 g_wkb[(size_t)H_ * DK_ * D_];
__device__ bf16 g_wvb[(size_t)H_ * DV_ * D_];
__device__ bf16 g_Q  [(size_t)B_ * N_ * HDK];
__device__ bf16 g_K  [(size_t)B_ * N_ * HDK];
__device__ bf16 g_V  [(size_t)B_ * N_ * HDV];
__device__ bf16 g_sim[(size_t)B_ * N_ * HN];   // lower-triangle tiles only

// ---------------- fragment types -------------------------------------------------
using FragA  = wmma::fragment<wmma::matrix_a, 16, 16, 16, bf16, wmma::row_major>;
using FragBc = wmma::fragment<wmma::matrix_b, 16, 16, 16, bf16, wmma::col_major>;
using FragBr = wmma::fragment<wmma::matrix_b, 16, 16, 16, bf16, wmma::row_major>;
using FragC  = wmma::fragment<wmma::accumulator, 16, 16, 16, float>;

// ---------------- cp.async helpers -----------------------------------------------
__device__ __forceinline__ uint32_t smem_u32(const void* p) {
    uint32_t a;
    asm("{ .reg .u64 t; cvta.to.shared.u64 t, %1; cvt.u32.u64 %0, t; }"
        : "=r"(a) : "l"(p));
    return a;
}
__device__ __forceinline__ void cp16(uint32_t dst, const void* src) {
    asm volatile("cp.async.cg.shared.global [%0], [%1], 16;"
                 :: "r"(dst), "l"(__cvta_generic_to_global(src)));
}
__device__ __forceinline__ void cp_commit() {
    asm volatile("cp.async.commit_group;" ::: "memory");
}
__device__ __forceinline__ void cp_wait2() {
    asm volatile("cp.async.wait_group 2;" ::: "memory");
}

// 128 rows x 32 cols K-major (row stride 40 elems), 128 threads, 4 cp16 each
__device__ __forceinline__ void ld_A(uint32_t sdst, const bf16* g, int ld, int tid) {
#pragma unroll
    for (int i = 0; i < 4; ++i) {
        int u = tid + i * 128;
        int r = u >> 2, c = (u & 3) * 8;
        cp16(sdst + (uint32_t)(r * (A_STRIDE * 2) + c * 2), g + (size_t)r * ld + c);
    }
}
// 64 rows x 32 cols K-major (row stride 40 elems), 128 threads, 2 cp16 each
__device__ __forceinline__ void ld_A64(uint32_t sdst, const bf16* g, int ld, int tid) {
#pragma unroll
    for (int i = 0; i < 2; ++i) {
        int u = tid + i * 128;
        int r = u >> 2, c = (u & 3) * 8;
        cp16(sdst + (uint32_t)(r * (A_STRIDE * 2) + c * 2), g + (size_t)r * ld + c);
    }
}
// 32 rows(k) x 128 cols(n) row-major (row stride 136 elems), 128 threads
__device__ __forceinline__ void ld_Brow(uint32_t sdst, const bf16* g, int ld, int tid) {
#pragma unroll
    for (int i = 0; i < 4; ++i) {
        int u = tid + i * 128;
        int r = u >> 4, c = (u & 15) * 8;
        cp16(sdst + (uint32_t)(r * (B_ROW_STRIDE * 2) + c * 2), g + (size_t)r * ld + c);
    }
}

// ---------------- MMA micro-steps --------------------------------------------------
// warp tile 64x64, NT (B col-major view, stride 40)
__device__ __forceinline__ void mma_w64(FragC acc[4][4], const bf16* As, const bf16* Bs,
                                        int wm, int wn) {
#pragma unroll
    for (int ks = 0; ks < 32; ks += 16) {
        FragA a[4];
#pragma unroll
        for (int i = 0; i < 4; ++i)
            wmma::load_matrix_sync(a[i], As + (wm * 64 + i * 16) * A_STRIDE + ks, A_STRIDE);
#pragma unroll
        for (int j = 0; j < 4; ++j) {
            FragBc b;
            wmma::load_matrix_sync(b, Bs + (wn * 64 + j * 16) * A_STRIDE + ks, A_STRIDE);
#pragma unroll
            for (int i = 0; i < 4; ++i)
                wmma::mma_sync(acc[i][j], a[i], b, acc[i][j]);
        }
    }
}
// warp tile 32x64, B row-major (stride 136) — AV
__device__ __forceinline__ void mma_av(FragC acc[2][4], const bf16* As, const bf16* Bs,
                                       int wm, int wn) {
#pragma unroll
    for (int ks = 0; ks < 32; ks += 16) {
        FragA a[2];
        wmma::load_matrix_sync(a[0], As + (wm * 32) * A_STRIDE + ks,      A_STRIDE);
        wmma::load_matrix_sync(a[1], As + (wm * 32 + 16) * A_STRIDE + ks, A_STRIDE);
#pragma unroll
        for (int j = 0; j < 4; ++j) {
            FragBr b;
            wmma::load_matrix_sync(b, Bs + ks * B_ROW_STRIDE + wn * 64 + j * 16, B_ROW_STRIDE);
            wmma::mma_sync(acc[0][j], a[0], b, acc[0][j]);
            wmma::mma_sync(acc[1][j], a[1], b, acc[1][j]);
        }
    }
}

// ---------------- pipelined NT mainloop (128x128, 128 threads) ---------------------
__device__ __forceinline__ void loop_nt(FragC acc[4][4], char* dsm,
                                        const bf16* A, int lda,
                                        const bf16* Bp, int ldb,
                                        int nk, int tid, int wm, int wn) {
    uint32_t sb = smem_u32(dsm);
#pragma unroll
    for (int s = 0; s < 3; ++s) {
        if (s < nk) {
            ld_A(sb + s * STAGE_BYTES,         A  + s * 32, lda, tid);
            ld_A(sb + s * STAGE_BYTES + 10240, Bp + s * 32, ldb, tid);
        }
        cp_commit();
    }
    for (int i = 0; i < nk; ++i) {
        cp_wait2();
        __syncthreads();
        int ci = i + 3;
        if (ci < nk) {
            uint32_t st = sb + (uint32_t)(ci & 3) * STAGE_BYTES;
            ld_A(st,         A  + ci * 32, lda, tid);
            ld_A(st + 10240, Bp + ci * 32, ldb, tid);
        }
        cp_commit();
        const bf16* As = reinterpret_cast<const bf16*>(dsm + (i & 3) * STAGE_BYTES);
        mma_w64(acc, As, As + 10240 / 2, wm, wn);
    }
    __syncthreads();
}

// ---------------- epilogues (128 threads) ------------------------------------------
__device__ __forceinline__ void stage_acc16(FragC acc[4][4], float* stg, int wm, int wn) {
#pragma unroll
    for (int i = 0; i < 4; ++i)
#pragma unroll
        for (int j = 0; j < 4; ++j)
            wmma::store_matrix_sync(stg + (wm * 64 + i * 16) * EP_STRIDE + wn * 64 + j * 16,
                                    acc[i][j], EP_STRIDE, wmma::mem_row_major);
}

// MODE 0: plain bf16. MODE 1: causal relu/N bf16.
template <int MODE>
__device__ __forceinline__ void ep_bf16(FragC acc[4][4], char* dsm, bf16* C, int ldc,
                                        int q0, int m0, int tid, int wm, int wn) {
    float* stg = reinterpret_cast<float*>(dsm);
    stage_acc16(acc, stg, wm, wn);
    __syncthreads();
    const float inv_n = 1.0f / (float)N_;
#pragma unroll
    for (int it = 0; it < 16; ++it) {
        int idx = it * 128 + tid;
        int r = idx >> 4, cv = idx & 15;
        const float* p = stg + r * EP_STRIDE + cv * 8;
        union { bf16 v[8]; uint4 u4; } pk;
#pragma unroll
        for (int e = 0; e < 8; ++e) {
            float v = p[e];
            if (MODE == 1) {
                int gm = m0 + cv * 8 + e;
                v = (gm <= q0 + r) ? fmaxf(v, 0.0f) * inv_n : 0.0f;
            }
            pk.v[e] = __float2bfloat16(v);
        }
        *reinterpret_cast<uint4*>(C + (size_t)r * ldc + cv * 8) = pk.u4;
    }
    __syncthreads();
}

// ---------------- kernels ---------------------------------------------------------
__global__ void f2bf_kernel(const float4* __restrict__ in,
                            __nv_bfloat162* __restrict__ out, int n4) {
    int i0 = (blockIdx.x * blockDim.x + threadIdx.x) * 2;
#pragma unroll
    for (int k = 0; k < 2; ++k) {
        int i = i0 + k;
        if (i < n4) {
            float4 v = in[i];
            out[2 * i]     = __floats2bfloat162_rn(v.x, v.y);
            out[2 * i + 1] = __floats2bfloat162_rn(v.z, v.w);
        }
    }
}

__global__ __launch_bounds__(128) void k_proj(const bf16* __restrict__ A0,
                                              const bf16* __restrict__ W,
                                              bf16* __restrict__ C0, int ldc) {
    extern __shared__ char dsm[];
    int tid = threadIdx.x, wid = tid >> 5;
    int wm = wid & 1, wn = wid >> 1;
    const bf16* A  = A0 + (size_t)blockIdx.y * 128 * D_;
    const bf16* Bp = W  + (size_t)blockIdx.x * 128 * D_;
    bf16* C = C0 + (size_t)(blockIdx.y * 128) * ldc + blockIdx.x * 128;

    FragC acc[4][4];
#pragma unroll
    for (int i = 0; i < 4; ++i)
#pragma unroll
        for (int j = 0; j < 4; ++j) wmma::fill_fragment(acc[i][j], 0.0f);

    loop_nt(acc, dsm, A, D_, Bp, D_, D_ / 32, tid, wm, wn);
    ep_bf16<0>(acc, dsm, C, ldc, 0, 0, tid, wm, wn);
}

__global__ __launch_bounds__(128) void k_scores(const bf16* __restrict__ Q,
                                                const bf16* __restrict__ Kx,
                                                bf16* __restrict__ sim) {
    int mt = blockIdx.x, nt = blockIdx.y;
    if (mt > nt) return;                       // upper tiles never read by AV
    int b = blockIdx.z >> 3, h = blockIdx.z & 7;
    extern __shared__ char dsm[];
    int tid = threadIdx.x, wid = tid >> 5;
    int wm = wid & 1, wn = wid >> 1;

    const bf16* A  = Q  + ((size_t)(b * N_ + nt * 128)) * HDK + h * DK_;
    const bf16* Bp = Kx + ((size_t)(b * N_ + mt * 128)) * HDK + h * DK_;
    bf16* C = sim + ((size_t)(b * N_ + nt * 128)) * HN + (size_t)h * N_ + mt * 128;

    FragC acc[4][4];
#pragma unroll
    for (int i = 0; i < 4; ++i)
#pragma unroll
        for (int j = 0; j < 4; ++j) wmma::fill_fragment(acc[i][j], 0.0f);

    loop_nt(acc, dsm, A, HDK, Bp, HDK, DK_ / 32, tid, wm, wn);
    ep_bf16<1>(acc, dsm, C, HN, nt * 128, mt * 128, tid, wm, wn);
}

// AV: 64-row tiles paired (t64, 31-t64) -> 256 uniform blocks of 33 units each,
// all co-resident (>=2 CTAs/SM, 2 warps/SMSP, zero tail).
__global__ __launch_bounds__(128) void k_av64(const bf16* __restrict__ sim,
                                              const bf16* __restrict__ V,
                                              const float* __restrict__ x,
                                              float* __restrict__ out) {
    int vt = blockIdx.x, pair = blockIdx.y, b = blockIdx.z;
    extern __shared__ char dsm[];
    uint32_t sb = smem_u32(dsm);
    int tid = threadIdx.x, wid = tid >> 5;
    int wm = wid & 1, wn = wid >> 1;     // warp tile 32x64 over 64x128 output

    const bf16* Vb = V + (size_t)b * N_ * HDV + vt * 128;
    int tiles2[2] = {31 - pair, pair};   // heavy tile first

#pragma unroll
    for (int t = 0; t < 2; ++t) {
        int t64 = tiles2[t];
        const bf16* Arow = sim + ((size_t)(b * N_ + t64 * 64)) * HN;
        const int nkh = (t64 + 1) * 2;   // K=32 chunks per head (causal bound)
        const int nk  = nkh * H_;        // >= 16

        FragC acc[2][4];
#pragma unroll
        for (int i = 0; i < 2; ++i)
#pragma unroll
            for (int j = 0; j < 4; ++j) wmma::fill_fragment(acc[i][j], 0.0f);

#pragma unroll
        for (int s = 0; s < 3; ++s) {
            int h = s / nkh, kc = s - h * nkh;
            ld_A64 (sb + s * AV_STAGE, Arow + h * N_ + kc * 32, HN, tid);
            ld_Brow(sb + s * AV_STAGE + AV_A_BYTES,
                    Vb + (size_t)(kc * 32) * HDV + h * DV_, HDV, tid);
            cp_commit();
        }
        for (int i = 0; i < nk; ++i) {
            cp_wait2();
            __syncthreads();
            int ci = i + 3;
            if (ci < nk) {
                int h = ci / nkh, kc = ci - h * nkh;
                uint32_t st = sb + (uint32_t)(ci & 3) * AV_STAGE;
                ld_A64 (st, Arow + h * N_ + kc * 32, HN, tid);
                ld_Brow(st + AV_A_BYTES, Vb + (size_t)(kc * 32) * HDV + h * DV_, HDV, tid);
            }
            cp_commit();
            const bf16* As = reinterpret_cast<const bf16*>(dsm + (i & 3) * AV_STAGE);
            mma_av(acc, As, As + AV_A_BYTES / 2, wm, wn);
        }
        __syncthreads();

        // epilogue: stage 64x136 fp32, residual add, float4 stores
        float* stg = reinterpret_cast<float*>(dsm);
#pragma unroll
        for (int i = 0; i < 2; ++i)
#pragma unroll
            for (int j = 0; j < 4; ++j)
                wmma::store_matrix_sync(stg + (wm * 32 + i * 16) * EP_STRIDE + wn * 64 + j * 16,
                                        acc[i][j], EP_STRIDE, wmma::mem_row_major);
        __syncthreads();
        size_t rowbase = (size_t)(b * N_ + t64 * 64);
#pragma unroll
        for (int it = 0; it < 16; ++it) {
            int idx = it * 128 + tid;
            int r = idx >> 5, cv = idx & 31;
            size_t o = (rowbase + r) * (size_t)DV_ + vt * 128 + cv * 4;
            float4 xv = *reinterpret_cast<const float4*>(x + o);
            const float* p = stg + r * EP_STRIDE + cv * 4;
            float4 ov = make_float4(xv.x + p[0], xv.y + p[1], xv.z + p[2], xv.w + p[3]);
            *reinterpret_cast<float4*>(out + o) = ov;
        }
        __syncthreads();
    }
}

// ---------------- host launcher ---------------------------------------------------
static void conv_launch(const float* src, bf16* dst, int n) {
    int n4 = n / 4;
    int nthread = (n4 + 1) / 2;
    f2bf_kernel<<<(nthread + 255) / 256, 256>>>(
        reinterpret_cast<const float4*>(src),
        reinterpret_cast<__nv_bfloat162*>(dst), n4);
}

extern "C" void kernel_launch(void* const* d_in, const int* in_sizes, int n_in,
                              void* d_out, int out_size) {
    (void)in_sizes; (void)n_in; (void)out_size;
    const float* x  = (const float*)d_in[0];
    const float* Wq = (const float*)d_in[1];
    const float* Wk = (const float*)d_in[2];
    const float* Wv = (const float*)d_in[3];

    bf16 *xb, *wqb, *wkb, *wvb, *Q, *K, *V, *sim;
    cudaGetSymbolAddress((void**)&xb,  g_xb);
    cudaGetSymbolAddress((void**)&wqb, g_wqb);
    cudaGetSymbolAddress((void**)&wkb, g_wkb);
    cudaGetSymbolAddress((void**)&wvb, g_wvb);
    cudaGetSymbolAddress((void**)&Q,   g_Q);
    cudaGetSymbolAddress((void**)&K,   g_K);
    cudaGetSymbolAddress((void**)&V,   g_V);
    cudaGetSymbolAddress((void**)&sim, g_sim);

    cudaFuncSetAttribute(k_proj,   cudaFuncAttributeMaxDynamicSharedMemorySize, DSMEM);
    cudaFuncSetAttribute(k_scores, cudaFuncAttributeMaxDynamicSharedMemorySize, DSMEM);
    cudaFuncSetAttribute(k_av64,   cudaFuncAttributeMaxDynamicSharedMemorySize, AV_DSMEM);

    conv_launch(x,  xb,  B_ * N_ * D_);
    conv_launch(Wq, wqb, H_ * DK_ * D_);
    conv_launch(Wk, wkb, H_ * DK_ * D_);
    conv_launch(Wv, wvb, H_ * DV_ * D_);

    // Q = x Wq^T, K = x Wk^T, V = x Wv^T
    k_proj<<<dim3(HDK / 128, (B_ * N_) / 128), 128, DSMEM>>>(xb, wqb, Q, HDK);
    k_proj<<<dim3(HDK / 128, (B_ * N_) / 128), 128, DSMEM>>>(xb, wkb, K, HDK);
    k_proj<<<dim3(HDV / 128, (B_ * N_) / 128), 128, DSMEM>>>(xb, wvb, V, HDV);

    // sim = causal relu(Q K^T)/N  (lower-triangle tiles only)
    k_scores<<<dim3(16, 16, 16), 128, DSMEM>>>(Q, K, sim);

    // out = x + sim V  (256 uniform paired blocks, all co-resident)
    k_av64<<<dim3(8, 16, 2), 128, AV_DSMEM>>>(sim, V, x, (float*)d_out);
}